// round 15
// baseline (speedup 1.0000x reference)
#include <cuda_runtime.h>

#define BB   8192
#define CC   2514
#define NN   2513      // number of foreground classes
#define TPB  128       // k_row threads (10 float2 per thread)
#define P_EXP 0.8f
#define LOG_EPS -4.6051701859880914f   // log(0.01)
#define NEG_BIG -1e30f
#define TOTAL4 ((BB * CC) / 4)         // 5,148,672 float4 in target
#define LGRID  4096
#define LSTR   (LGRID * 256)           // 1,048,576 threads; 5 float4 each
#define CP_PAD 2608                    // padded cp table (max read idx 2559)

__device__ int   g_hist[NN];           // zero-init; reset by k_cp after use
__device__ int   g_labels[BB];
__device__ __align__(8) float g_cp[CP_PAD];  // g_cp[col]=cum_c[col-1]^P; [0]=1; pad=1
__device__ float g_inv;                // 1 / (#foreground rows), or 0

__device__ __forceinline__ void pdl_wait()    { asm volatile("griddepcontrol.wait;" ::: "memory"); }
__device__ __forceinline__ void pdl_trigger() { asm volatile("griddepcontrol.launch_dependents;" ::: "memory"); }

// ---------------------------------------------------------------------------
// One-hot scan: 5 front-batched LDG.128 per thread (MLP=5, 28 regs).
// Trigger at TOP: dependents may launch immediately; their pdl_wait still
// blocks until this whole grid (and its atomics) completes.
__global__ void __launch_bounds__(256) k_labels(const float4* __restrict__ t) {
    pdl_trigger();                         // let k_cp (and transitively k_row) launch now

    const int idx = blockIdx.x * 256 + threadIdx.x;

    float4 v[5];
    #pragma unroll
    for (int k = 0; k < 5; k++) {
        int i = idx + k * LSTR;             // only k==4 can exceed TOTAL4
        if (k < 4 || i < TOTAL4) v[k] = __ldg(t + i);
        else v[k] = make_float4(0.f, 0.f, 0.f, 0.f);
    }

    #pragma unroll
    for (int k = 0; k < 5; k++) {
        float mx = fmaxf(fmaxf(v[k].x, v[k].y), fmaxf(v[k].z, v[k].w));
        if (mx > 0.f) {
            float vv[4] = {v[k].x, v[k].y, v[k].z, v[k].w};
            #pragma unroll
            for (int e = 0; e < 4; e++) {
                if (vv[e] > 0.f) {
                    int flat = 4 * (idx + k * LSTR) + e;
                    int row  = flat / CC;
                    int col  = flat - row * CC;
                    g_labels[row] = col;
                    if (col > 0) atomicAdd(&g_hist[col - 1], 1);
                }
            }
        }
    }
}

// ---------------------------------------------------------------------------
// Single block: builds cp table, counts foreground rows (c = sum hist),
// publishes g_inv = 1/c, zeroes out[0], resets hist for the next replay.
// Trigger at TOP so k_row launches (and runs its whole pass 1) while we wait.
__global__ void __launch_bounds__(1024) k_cp(const float* __restrict__ cum_samples,
                                             float* __restrict__ out) {
    pdl_trigger();                         // k_row may launch + do pass 1 now
    pdl_wait();                            // k_labels' hist/labels visible

    __shared__ int shc[32];
    const int tid = threadIdx.x;

    int c = 0;
    #pragma unroll
    for (int k = 0; k < 3; k++) {          // 3*1024 = 3072 >= CP_PAD-1
        int i = tid + k * 1024;
        if (i < NN) {
            int h = g_hist[i];
            c += h;
            float cc = fmaxf(cum_samples[i] + (float)h, 1.0f);
            g_cp[i + 1] = __expf(P_EXP * __logf(cc));
            g_hist[i] = 0;                 // ready for next graph replay
        } else if (i + 1 < CP_PAD) {
            g_cp[i + 1] = 1.f;             // pad: only ever multiplied by e=0
        }
    }

    #pragma unroll
    for (int o = 16; o > 0; o >>= 1)
        c += __shfl_xor_sync(0xffffffffu, c, o);
    if ((tid & 31) == 0) shc[tid >> 5] = c;
    __syncthreads();
    if (tid < 32) {
        int r = shc[tid];
        #pragma unroll
        for (int o = 16; o > 0; o >>= 1)
            r += __shfl_xor_sync(0xffffffffu, r, o);
        if (tid == 0) {
            g_cp[0] = 1.f;
            g_inv   = (r > 0) ? (1.f / (float)r) : 0.f;
            out[0]  = 0.f;                 // k_row accumulates into this
        }
    }
}

// ---------------------------------------------------------------------------
__device__ __forceinline__ float blockSum(float v, float* sh) {
    #pragma unroll
    for (int o = 16; o > 0; o >>= 1)
        v += __shfl_xor_sync(0xffffffffu, v, o);
    if ((threadIdx.x & 31) == 0) sh[threadIdx.x >> 5] = v;
    __syncthreads();
    if (threadIdx.x < 32) {
        float r = (threadIdx.x < (TPB / 32)) ? sh[threadIdx.x] : 0.f;
        #pragma unroll
        for (int o = 2; o > 0; o >>= 1)    // TPB/32 = 4 partials
            r += __shfl_xor_sync(0xffffffffu, r, o);
        if (threadIdx.x == 0) sh[0] = r;
    }
    __syncthreads();
    return sh[0];
}

// One block (128 threads) per row. ALL label-independent work (x loads, exp,
// softmax-denominator reduction) runs BEFORE the PDL wait; only the
// label/cp-dependent scalars and pass 2 are on the dependent critical path.
__global__ void __launch_bounds__(TPB, 8) k_row(const float* __restrict__ x,
                                                float* __restrict__ out) {
    const int row = blockIdx.x;
    const int tid = threadIdx.x;

    __shared__ float shA[4];
    __shared__ float shB[4];

    const float2* p  = reinterpret_cast<const float2*>(x + (size_t)row * CC);
    const float2* pc = reinterpret_cast<const float2*>(g_cp);
    const int NF2 = CC / 2;                // 1257 float2 per row

    // --- prefetch x (independent of prior kernels) ---
    float2 v[10];
    #pragma unroll
    for (int k = 0; k < 10; k++) {
        int i = tid + k * TPB;
        if (k < 9 || i < NF2) v[k] = __ldg(p + i);
        else { v[k].x = NEG_BIG; v[k].y = NEG_BIG; }
    }
    if (tid == 0) v[0].x = NEG_BIG;        // mask background column 0 (static)

    // --- pass 1 (label-independent): e = exp(x), block-sum ---
    float s = 0.f;
    #pragma unroll
    for (int k = 0; k < 10; k++) {
        v[k].x = __expf(v[k].x);
        v[k].y = __expf(v[k].y);
        s += v[k].x + v[k].y;
    }
    float S = blockSum(s, shA);
    float logS = __logf(S);

    pdl_wait();                            // labels + cp now visible

    const int label = g_labels[row];
    if (label == 0) return;                // background row: excluded

    float xl    = __ldg(x + (size_t)row * CC + label);   // broadcast
    float rcp_l = 1.f / __ldg(&g_cp[label]);
    float ls    = fmaxf(xl - logS, LOG_EPS);
    float K     = __expf(-2.f * (logS + ls));

    // --- pass 2: straight-line FMA, no bounds checks (cp padded; e=0 tail) ---
    float s2 = 0.f;
    #pragma unroll
    for (int k = 0; k < 10; k++) {
        int i = tid + k * TPB;
        float2 cp = __ldg(pc + i);         // max i = 1279 -> idx 2559 < CP_PAD
        float ex = v[k].x, ey = v[k].y;
        float mitx = fminf(1.f, cp.x * rcp_l);
        float mity = fminf(1.f, cp.y * rcp_l);
        float cmx  = fmaxf(1.f, ex * ex * K);
        float cmy  = fmaxf(1.f, ey * ey * K);
        s2 += ex * mitx * cmx + ey * mity * cmy;
    }
    float S2 = blockSum(s2, shB);

    if (tid == 0)
        atomicAdd(out, (__logf(S2) - xl) * g_inv);
}

// ---------------------------------------------------------------------------
extern "C" void kernel_launch(void* const* d_in, const int* in_sizes, int n_in,
                              void* d_out, int out_size) {
    const float* x   = (const float*)d_in[0];   // input  [B, C]
    const float* t   = (const float*)d_in[1];   // target [B, C] (one-hot)
    const float* cum = (const float*)d_in[2];   // cum_samples [NN]
    float* out = (float*)d_out;
    (void)in_sizes; (void)n_in; (void)out_size;

    k_labels<<<LGRID, 256>>>((const float4*)t);

    cudaLaunchAttribute attr[1];
    attr[0].id = cudaLaunchAttributeProgrammaticStreamSerialization;
    attr[0].val.programmaticStreamSerializationAllowed = 1;

    {
        cudaLaunchConfig_t cfg = {};
        cfg.gridDim  = dim3(1, 1, 1);
        cfg.blockDim = dim3(1024, 1, 1);
        cfg.attrs    = attr;
        cfg.numAttrs = 1;
        cudaLaunchKernelEx(&cfg, k_cp, cum, out);
    }
    {
        cudaLaunchConfig_t cfg = {};
        cfg.gridDim  = dim3(BB, 1, 1);
        cfg.blockDim = dim3(TPB, 1, 1);
        cfg.attrs    = attr;
        cfg.numAttrs = 1;
        cudaLaunchKernelEx(&cfg, k_row, (const float*)x, out);
    }
}